// round 17
// baseline (speedup 1.0000x reference)
#include <cuda_runtime.h>
#include <cuda_bf16.h>
#include <cuda_fp16.h>
#include <cstdint>

#define BB 8
#define CC 96
#define HH 512
#define WW 96
#define HWX (HH*WW)     // 49152
#define OC  288
#define NT  768         // 24 warps
#define NROWS (BB*HH)   // 4096
#define GRID 152        // persistent: one CTA per SM

typedef unsigned int u32;
typedef unsigned short u16;

// prep outputs: W' (BN folded) in EXACT mma A-fragment order, hi/lo bf16 planes
__device__ u32   g_WfragH[108*32*4];
__device__ u32   g_WfragL[108*32*4];
__device__ float g_bias[OC];

// ---- smem map (bytes). 16-bit planes: 96 rows x 104 elems (stride 208B) ----
#define PL   208
#define PLSZ (96*PL)        // 19968
#define O_XBH 0             // x split hi [c][w] (B for QKV; residual source)
#define O_XBL (PLSZ)
#define O_QH  (2*PLSZ)      // q hi [o][w]  (A for score via trans-ldmatrix)
#define O_QL  (3*PLSZ)
#define O_KH  (4*PLSZ)      // k hi [c][w]  (B for score)
#define O_KL  (5*PLSZ)
#define O_ATH (4*PLSZ)      // attn fp16 [qw][kw] (K area, safe after barrier 3)
#define O_VTH (6*PLSZ)      // vT fp16 single plane [w][c] (B for AV)
#define O_PM  (8*PLSZ)      // softmax partials [96][4] float2 = 3072 B
#define O_XST (8*PLSZ + 3072)  // next-row x staging (raw f32): 36864 B
#define SMEM_BYTES (O_XST + 36864)   // 199680

__device__ __forceinline__ u32 smem_u32(const void* p){
    u32 a; asm("{ .reg .u64 t; cvta.to.shared.u64 t, %1; cvt.u32.u64 %0, t; }" : "=r"(a) : "l"(p));
    return a;
}
#define LDSM4(r0,r1,r2,r3,addr) \
    asm volatile("ldmatrix.sync.aligned.m8n8.x4.shared.b16 {%0,%1,%2,%3}, [%4];" \
        : "=r"(r0),"=r"(r1),"=r"(r2),"=r"(r3) : "r"(addr))
#define LDSM4T(r0,r1,r2,r3,addr) \
    asm volatile("ldmatrix.sync.aligned.m8n8.x4.trans.shared.b16 {%0,%1,%2,%3}, [%4];" \
        : "=r"(r0),"=r"(r1),"=r"(r2),"=r"(r3) : "r"(addr))
#define LDSM2T(r0,r1,addr) \
    asm volatile("ldmatrix.sync.aligned.m8n8.x2.trans.shared.b16 {%0,%1}, [%2];" \
        : "=r"(r0),"=r"(r1) : "r"(addr))
#define MMA_BF16(d,a0,a1,a2,a3,b0,b1) \
    asm volatile("mma.sync.aligned.m16n8k16.row.col.f32.bf16.bf16.f32 " \
        "{%0,%1,%2,%3},{%4,%5,%6,%7},{%8,%9},{%0,%1,%2,%3};" \
        : "+f"((d)[0]),"+f"((d)[1]),"+f"((d)[2]),"+f"((d)[3]) \
        : "r"(a0),"r"(a1),"r"(a2),"r"(a3),"r"(b0),"r"(b1))
#define MMA_F16(d,a0,a1,a2,a3,b0,b1) \
    asm volatile("mma.sync.aligned.m16n8k16.row.col.f32.f16.f16.f32 " \
        "{%0,%1,%2,%3},{%4,%5,%6,%7},{%8,%9},{%0,%1,%2,%3};" \
        : "+f"((d)[0]),"+f"((d)[1]),"+f"((d)[2]),"+f"((d)[3]) \
        : "r"(a0),"r"(a1),"r"(a2),"r"(a3),"r"(b0),"r"(b1))
#define NBAR(id) asm volatile("bar.sync %0, 128;" :: "r"(id) : "memory")
__device__ __forceinline__ void cp_async16(u32 dst, const void* src){
    asm volatile("cp.async.cg.shared.global [%0], [%1], 16;" :: "r"(dst), "l"(src));
}
#define CP_COMMIT() asm volatile("cp.async.commit_group;" ::: "memory")
#define CP_WAIT0()  asm volatile("cp.async.wait_group 0;" ::: "memory")

__device__ __forceinline__ void split2(float f, u16& h, u16& l){
    __nv_bfloat16 bh = __float2bfloat16_rn(f);
    float r = f - __bfloat162float(bh);
    __nv_bfloat16 bl = __float2bfloat16_rn(r);
    h = __bfloat16_as_ushort(bh); l = __bfloat16_as_ushort(bl);
}

// one k16 step for a 24-col quarter: 9 bf16 MMAs (hh, hl, lh), B frags passed in
__device__ __forceinline__ void kt_mma(float (&acc)[3][4],
        u32 ah0,u32 ah1,u32 ah2,u32 ah3,
        u32 al0,u32 al1,u32 al2,u32 al3,
        u32 h0,u32 h1,u32 h2,u32 h3,u32 g0,u32 g1,
        u32 l0,u32 l1,u32 l2,u32 l3,u32 m0,u32 m1){
    MMA_BF16(acc[0], ah0,ah1,ah2,ah3, h0,h1);
    MMA_BF16(acc[1], ah0,ah1,ah2,ah3, h2,h3);
    MMA_BF16(acc[2], ah0,ah1,ah2,ah3, g0,g1);
    MMA_BF16(acc[0], ah0,ah1,ah2,ah3, l0,l1);
    MMA_BF16(acc[1], ah0,ah1,ah2,ah3, l2,l3);
    MMA_BF16(acc[2], ah0,ah1,ah2,ah3, m0,m1);
    MMA_BF16(acc[0], al0,al1,al2,al3, h0,h1);
    MMA_BF16(acc[1], al0,al1,al2,al3, h2,h3);
    MMA_BF16(acc[2], al0,al1,al2,al3, g0,g1);
}

// ---------------- prep: bias ----------------
__global__ void prep_bias(const float* __restrict__ qkv_w, const float* __restrict__ qkv_b,
                          const float* __restrict__ gam, const float* __restrict__ bet,
                          const float* __restrict__ mn,  const float* __restrict__ vr){
    int o = blockIdx.x;
    int c = threadIdx.x;
    __shared__ float red[CC];
    float inv   = gam[c] * rsqrtf(vr[c] + 1e-5f);
    float shift = bet[c] - mn[c]*inv;
    red[c] = qkv_w[o*CC + c] * shift;
    __syncthreads();
    if (c < 32){
        float s = red[c] + red[c+32] + red[c+64];
        #pragma unroll
        for (int off = 16; off; off >>= 1) s += __shfl_down_sync(0xffffffffu, s, off);
        if (c == 0) g_bias[o] = s + qkv_b[o];
    }
}

// ---------------- prep: W' in A-fragment order ----------------
__global__ void prep_frag(const float* __restrict__ qkv_w,
                          const float* __restrict__ gam, const float* __restrict__ vr){
    int blk = blockIdx.x;          // 108 = p*36 + mt*6 + kt
    int p  = blk / 36;
    int mt = (blk / 6) % 6;
    int kt = blk % 6;
    int lane = threadIdx.x;
    int r  = lane >> 2;
    int c0 = 2*(lane & 3);
    int base = (blk*32 + lane)*4;
    #pragma unroll
    for (int q = 0; q < 4; ++q){
        int ro = mt*16 + r + (q & 1)*8;
        int co = kt*16 + c0 + (q >> 1)*8;
        float inv0 = gam[co]   * rsqrtf(vr[co]   + 1e-5f);
        float inv1 = gam[co+1] * rsqrtf(vr[co+1] + 1e-5f);
        u16 h0,l0,h1,l1;
        split2(qkv_w[(p*CC + ro)*CC + co]   * inv0, h0, l0);
        split2(qkv_w[(p*CC + ro)*CC + co+1] * inv1, h1, l1);
        g_WfragH[base + q] = (u32)h0 | ((u32)h1 << 16);
        g_WfragL[base + q] = (u32)l0 | ((u32)l1 << 16);
    }
}

// ---------------- fused attention kernel ----------------
__global__ __launch_bounds__(NT) void attn_kernel(const float* __restrict__ x,
                                                  float* __restrict__ out){
    extern __shared__ char smc[];
    const int t    = threadIdx.x;
    const int lane = t & 31;
    const int warp = t >> 5;     // 0..23
    const int mt = warp >> 2;    // 0..5
    const int nq = warp & 3;     // 0..3
    const int g  = lane >> 2;    // 0..7
    const int tq = lane & 3;     // 0..3

    const int ai = lane >> 3, ar = lane & 7;
    // A-side non-trans (attn [qw][kw] layout)
    const u32 aOff = (u32)((mt*16 + (ai&1)*8 + ar)*PL + ((ai>>1)*8)*2);
    // A-side TRANS (q stored [c][w]; tiles: (c0-7,m0-7),(c0-7,m8-15),(c8-15,m0-7),(c8-15,m8-15))
    const u32 aOffT = (u32)(((lane & 7) + ((lane >> 4)&1)*8)*PL + mt*32 + ((lane >> 3)&1)*16);
    // B-side lane offsets: x4-trans (16 cols) and x2-trans (last 8 cols)
    const u32 bRow  = (u32)(((lane & 7) + ((lane >> 3) & 1)*8)*PL);
    const u32 bOff4 = bRow + (u32)(nq*48 + ((lane >> 4)&1)*16);
    const u32 bOff2 = (u32)((((lane & 15) & 7) + (((lane & 15) >> 3))*8)*PL) + (u32)(nq*48 + 32);

    const u32 sb = smem_u32(smc);
    const int qw0 = mt*16 + g;

    // ---- prefetch first row into XSTAGE ----
    {
        const int bh0 = blockIdx.x;
        const size_t basep = (size_t)(bh0 >> 9)*CC*HWX + (size_t)(bh0 & 511)*WW;
        for (int idx = t; idx < CC*24; idx += NT){
            int c = idx/24, j = idx%24;
            cp_async16(sb + O_XST + (u32)idx*16, x + basep + (size_t)c*HWX + 4*j);
        }
        CP_COMMIT();
    }

    for (int bh = blockIdx.x; bh < NROWS; bh += GRID){
        const size_t base = (size_t)(bh >> 9)*CC*HWX + (size_t)(bh & 511)*WW;

        // ---- consume staged x: split into XB planes [c][w] ----
        CP_WAIT0();
        for (int idx = t; idx < CC*24; idx += NT){
            int c = idx/24, j = idx%24;
            float4 v = *(const float4*)(smc + O_XST + idx*16);
            u16 hh[4], ll[4];
            split2(v.x, hh[0], ll[0]); split2(v.y, hh[1], ll[1]);
            split2(v.z, hh[2], ll[2]); split2(v.w, hh[3], ll[3]);
            u32 off = (u32)(c*PL + 8*j);
            *(u32*)(smc + O_XBH + off)     = (u32)hh[0] | ((u32)hh[1] << 16);
            *(u32*)(smc + O_XBH + off + 4) = (u32)hh[2] | ((u32)hh[3] << 16);
            *(u32*)(smc + O_XBL + off)     = (u32)ll[0] | ((u32)ll[1] << 16);
            *(u32*)(smc + O_XBL + off + 4) = (u32)ll[2] | ((u32)ll[3] << 16);
        }
        __syncthreads();   // (1) XB visible

        // ---- QKV: kt-outer, pass-inner; B fragments loaded ONCE per kt ----
        {
            float acc3[3][3][4];
            #pragma unroll
            for (int p = 0; p < 3; ++p){
                float bg  = g_bias[p*CC + qw0];
                float bg8 = g_bias[p*CC + qw0 + 8];
                #pragma unroll
                for (int n6 = 0; n6 < 3; ++n6){
                    acc3[p][n6][0] = bg;  acc3[p][n6][1] = bg;
                    acc3[p][n6][2] = bg8; acc3[p][n6][3] = bg8;
                }
            }
            const u32* WfH = g_WfragH + (mt*6)*128 + lane*4;
            const u32* WfL = g_WfragL + (mt*6)*128 + lane*4;

            #pragma unroll
            for (int kt = 0; kt < 6; ++kt){
                u32 h0,h1,h2,h3, g0,g1, l0,l1,l2,l3, m0,m1;
                LDSM4T(h0,h1,h2,h3, sb + O_XBH + bOff4 + (u32)(kt*16*PL));
                LDSM2T(g0,g1,       sb + O_XBH + bOff2 + (u32)(kt*16*PL));
                LDSM4T(l0,l1,l2,l3, sb + O_XBL + bOff4 + (u32)(kt*16*PL));
                LDSM2T(m0,m1,       sb + O_XBL + bOff2 + (u32)(kt*16*PL));
                #pragma unroll
                for (int p = 0; p < 3; ++p){
                    uint4 AH = *(const uint4*)(WfH + (p*36 + kt)*128);
                    uint4 AL = *(const uint4*)(WfL + (p*36 + kt)*128);
                    kt_mma(acc3[p], AH.x,AH.y,AH.z,AH.w, AL.x,AL.y,AL.z,AL.w,
                           h0,h1,h2,h3,g0,g1, l0,l1,l2,l3,m0,m1);
                }
            }

            // epilogues: q,k bf16 hi/lo packed [o][w]; v single fp16 transposed [w][o]
            #pragma unroll
            for (int p = 0; p < 3; ++p){
                #pragma unroll
                for (int n6 = 0; n6 < 3; ++n6){
                    int w0 = nq*24 + n6*8 + 2*tq;
                    int o0 = qw0;
                    u16 h0,l0;
                    if (p < 2){
                        int OH = p ? O_KH : O_QH;
                        int OL = p ? O_KL : O_QL;
                        u16 h1,l1;
                        split2(acc3[p][n6][0], h0, l0); split2(acc3[p][n6][1], h1, l1);
                        *(u32*)(smc + OH + o0*PL + w0*2) = (u32)h0 | ((u32)h1 << 16);
                        *(u32*)(smc + OL + o0*PL + w0*2) = (u32)l0 | ((u32)l1 << 16);
                        split2(acc3[p][n6][2], h0, l0); split2(acc3[p][n6][3], h1, l1);
                        *(u32*)(smc + OH + (o0+8)*PL + w0*2) = (u32)h0 | ((u32)h1 << 16);
                        *(u32*)(smc + OL + (o0+8)*PL + w0*2) = (u32)l0 | ((u32)l1 << 16);
                    } else {
                        // v: single fp16, transposed [w][o]
                        __half v0 = __float2half_rn(acc3[p][n6][0]);
                        __half v1 = __float2half_rn(acc3[p][n6][1]);
                        __half v2 = __float2half_rn(acc3[p][n6][2]);
                        __half v3 = __float2half_rn(acc3[p][n6][3]);
                        *(u16*)(smc + O_VTH + (w0  )*PL + o0*2) = __half_as_ushort(v0);
                        *(u16*)(smc + O_VTH + (w0+1)*PL + o0*2) = __half_as_ushort(v1);
                        *(u16*)(smc + O_VTH + (w0  )*PL + (o0+8)*2) = __half_as_ushort(v2);
                        *(u16*)(smc + O_VTH + (w0+1)*PL + (o0+8)*2) = __half_as_ushort(v3);
                    }
                }
            }
        }
        __syncthreads();   // (2) q, k, vT visible; XSTAGE reads done

        // ---- prefetch next row into XSTAGE (hidden behind score/softmax/AV) ----
        {
            int nxt = bh + GRID;
            if (nxt < NROWS){
                const size_t basep = (size_t)(nxt >> 9)*CC*HWX + (size_t)(nxt & 511)*WW;
                for (int idx = t; idx < CC*24; idx += NT){
                    int c = idx/24, j = idx%24;
                    cp_async16(sb + O_XST + (u32)idx*16, x + basep + (size_t)c*HWX + 4*j);
                }
                CP_COMMIT();
            }
        }

        float acc[3][4];

        // ---- score: A=q via TRANS ldmatrix from [c][w], B=k; regs only ----
        #pragma unroll
        for (int n6 = 0; n6 < 3; ++n6){
            acc[n6][0]=0.f; acc[n6][1]=0.f; acc[n6][2]=0.f; acc[n6][3]=0.f;
        }
        #pragma unroll
        for (int kt = 0; kt < 6; ++kt){
            u32 ah0,ah1,ah2,ah3, al0,al1,al2,al3;
            u32 h0,h1,h2,h3, g0,g1, l0,l1,l2,l3, m0,m1;
            LDSM4T(ah0,ah1,ah2,ah3, sb + O_QH + aOffT + (u32)(kt*16*PL));
            LDSM4T(al0,al1,al2,al3, sb + O_QL + aOffT + (u32)(kt*16*PL));
            LDSM4T(h0,h1,h2,h3, sb + O_KH + bOff4 + (u32)(kt*16*PL));
            LDSM2T(g0,g1,       sb + O_KH + bOff2 + (u32)(kt*16*PL));
            LDSM4T(l0,l1,l2,l3, sb + O_KL + bOff4 + (u32)(kt*16*PL));
            LDSM2T(m0,m1,       sb + O_KL + bOff2 + (u32)(kt*16*PL));
            kt_mma(acc, ah0,ah1,ah2,ah3, al0,al1,al2,al3,
                   h0,h1,h2,h3,g0,g1, l0,l1,l2,l3,m0,m1);
        }

        // ---- register softmax, stage 1: per-warp partials over 24 kw cols ----
        float eA[6], eB[6], mA, mB, sA, sB;
        {
            mA = fmaxf(fmaxf(fmaxf(acc[0][0],acc[0][1]), fmaxf(acc[1][0],acc[1][1])),
                       fmaxf(acc[2][0],acc[2][1]));
            mB = fmaxf(fmaxf(fmaxf(acc[0][2],acc[0][3]), fmaxf(acc[1][2],acc[1][3])),
                       fmaxf(acc[2][2],acc[2][3]));
            mA = fmaxf(mA, __shfl_xor_sync(0xffffffffu, mA, 1));
            mA = fmaxf(mA, __shfl_xor_sync(0xffffffffu, mA, 2));
            mB = fmaxf(mB, __shfl_xor_sync(0xffffffffu, mB, 1));
            mB = fmaxf(mB, __shfl_xor_sync(0xffffffffu, mB, 2));
            sA = 0.f; sB = 0.f;
            #pragma unroll
            for (int n6 = 0; n6 < 3; ++n6){
                eA[2*n6  ] = __expf(acc[n6][0] - mA); sA += eA[2*n6  ];
                eA[2*n6+1] = __expf(acc[n6][1] - mA); sA += eA[2*n6+1];
                eB[2*n6  ] = __expf(acc[n6][2] - mB); sB += eB[2*n6  ];
                eB[2*n6+1] = __expf(acc[n6][3] - mB); sB += eB[2*n6+1];
            }
            sA += __shfl_xor_sync(0xffffffffu, sA, 1);
            sA += __shfl_xor_sync(0xffffffffu, sA, 2);
            sB += __shfl_xor_sync(0xffffffffu, sB, 1);
            sB += __shfl_xor_sync(0xffffffffu, sB, 2);
            if (tq == 0){
                *(float2*)(smc + O_PM + (qw0  )*32 + nq*8) = make_float2(mA, sA);
                *(float2*)(smc + O_PM + (qw0+8)*32 + nq*8) = make_float2(mB, sB);
            }
        }
        __syncthreads();   // (3) partials visible; ALL q/K reads done CTA-wide

        // ---- softmax stage 2: combine, write single fp16 attn plane into K area ----
        {
            float4 a0 = *(const float4*)(smc + O_PM + (qw0  )*32);
            float4 a1 = *(const float4*)(smc + O_PM + (qw0  )*32 + 16);
            float4 b0 = *(const float4*)(smc + O_PM + (qw0+8)*32);
            float4 b1 = *(const float4*)(smc + O_PM + (qw0+8)*32 + 16);
            float MA = fmaxf(fmaxf(a0.x, a0.z), fmaxf(a1.x, a1.z));
            float MB = fmaxf(fmaxf(b0.x, b0.z), fmaxf(b1.x, b1.z));
            float SA = a0.y*__expf(a0.x-MA) + a0.w*__expf(a0.z-MA)
                     + a1.y*__expf(a1.x-MA) + a1.w*__expf(a1.z-MA);
            float SB = b0.y*__expf(b0.x-MB) + b0.w*__expf(b0.z-MB)
                     + b1.y*__expf(b1.x-MB) + b1.w*__expf(b1.z-MB);
            float fA = __expf(mA - MA) / SA;
            float fB = __expf(mB - MB) / SB;
            #pragma unroll
            for (int n6 = 0; n6 < 3; ++n6){
                int kw0 = nq*24 + n6*8 + 2*tq;
                __half2 pa = __floats2half2_rn(eA[2*n6]*fA, eA[2*n6+1]*fA);
                __half2 pb = __floats2half2_rn(eB[2*n6]*fB, eB[2*n6+1]*fB);
                *(u32*)(smc + O_ATH + (qw0  )*PL + kw0*2) = *(u32*)&pa;
                *(u32*)(smc + O_ATH + (qw0+8)*PL + kw0*2) = *(u32*)&pb;
            }
        }
        NBAR(mt + 1);      // (4) attn rows [16mt,16mt+16) complete within mt-group

        // ---- AV (fp16, 1-product): A=attn plane, B=vT plane ----
        #pragma unroll
        for (int n6 = 0; n6 < 3; ++n6){
            acc[n6][0]=0.f; acc[n6][1]=0.f; acc[n6][2]=0.f; acc[n6][3]=0.f;
        }
        #pragma unroll
        for (int kt = 0; kt < 6; ++kt){
            u32 ah0,ah1,ah2,ah3;
            u32 h0,h1,h2,h3, g0,g1;
            LDSM4(ah0,ah1,ah2,ah3, sb + O_ATH + aOff + kt*32);
            LDSM4T(h0,h1,h2,h3, sb + O_VTH + bOff4 + (u32)(kt*16*PL));
            LDSM2T(g0,g1,       sb + O_VTH + bOff2 + (u32)(kt*16*PL));
            MMA_F16(acc[0], ah0,ah1,ah2,ah3, h0,h1);
            MMA_F16(acc[1], ah0,ah1,ah2,ah3, h2,h3);
            MMA_F16(acc[2], ah0,ah1,ah2,ah3, g0,g1);
        }

        // ---- direct epilogue: residual from XB planes + STG.32 (coalesced 32B sectors) ----
        #pragma unroll
        for (int n6 = 0; n6 < 3; ++n6){
            int c0 = nq*24 + n6*8 + 2*tq;
            #pragma unroll
            for (int e = 0; e < 4; ++e){
                int c = c0 + (e & 1);
                int qw = qw0 + (e >> 1)*8;
                float xh = __bfloat162float(*(__nv_bfloat16*)(smc + O_XBH + c*PL + qw*2));
                float xl = __bfloat162float(*(__nv_bfloat16*)(smc + O_XBL + c*PL + qw*2));
                out[base + (size_t)c*HWX + qw] = acc[n6][e] + xh + xl;
            }
        }
        __syncthreads();   // (5) row done; XB/planes reusable next iteration
    }
}

extern "C" void kernel_launch(void* const* d_in, const int* in_sizes, int n_in,
                              void* d_out, int out_size){
    const float* x     = (const float*)d_in[0];
    const float* gam   = (const float*)d_in[1];
    const float* bet   = (const float*)d_in[2];
    const float* mn    = (const float*)d_in[3];
    const float* vr    = (const float*)d_in[4];
    const float* qkv_w = (const float*)d_in[5];
    const float* qkv_b = (const float*)d_in[6];
    float* out = (float*)d_out;

    cudaFuncSetAttribute(attn_kernel, cudaFuncAttributeMaxDynamicSharedMemorySize, SMEM_BYTES);

    prep_bias<<<OC, CC>>>(qkv_w, qkv_b, gam, bet, mn, vr);
    prep_frag<<<108, 32>>>(qkv_w, gam, vr);
    attn_kernel<<<GRID, NT, SMEM_BYTES>>>(x, out);
}